// round 9
// baseline (speedup 1.0000x reference)
#include <cuda_runtime.h>

// Problem constants (match reference setup_inputs)
#define N_NODES 50000
#define N_EDGES 800000
#define HID 32
#define HEADS 8
#define F0 (HID * HEADS)   // 256
#define OUT_DIM 16
#define NEG_SLOPE 0.2f
#define LN_EPS 1e-5f
#define PMAX ((N_NODES + 7) / 8)
#define FULL 0xffffffffu

// ---------------- static device scratch (no allocations allowed) ----------
__device__ float g_h0[N_NODES * HID];     // after in_layer
__device__ float g_hf0[N_NODES * F0];     // h0 @ W0 (per-head features, layer0)
__device__ float g_res0[N_NODES * F0];    // h0 @ Wr0 + br0
__device__ float g_h1[N_NODES * F0];      // layer0 output (post LN)
__device__ float g_as0[N_NODES * HEADS];
__device__ float g_ad0[N_NODES * HEADS];
__device__ float g_hf1[N_NODES * HID];    // h1 @ W1
__device__ float g_res1[N_NODES * HID];   // h1 @ Wr1 + br1
__device__ float g_as1[N_NODES];
__device__ float g_ad1[N_NODES];
__device__ int   g_deg[N_NODES];
__device__ int   g_off[N_NODES];
__device__ int   g_cur[N_NODES];
__device__ int   g_srt[N_EDGES];          // edge src sorted by dst (CSR)
__device__ float g_part[PMAX * HID];      // pooling partials
__device__ float g_pool[HID];

// ---------------- K1: in_layer + zero degree ------------------------------
__global__ void k_in(const float* __restrict__ x, const float* __restrict__ Win,
                     const float* __restrict__ bin, int n) {
    int idx = blockIdx.x * blockDim.x + threadIdx.x;
    if (idx >= n * HID) return;
    int i = idx >> 5, j = idx & 31;
    g_h0[idx] = fmaf(x[i], Win[j], bin[j]);
    if (j == 0) g_deg[i] = 0;
}

// ---------------- K2: histogram of dst ------------------------------------
// edge_index is stored as int32 by the harness (int64 inputs are narrowed).
__global__ void k_hist(const int* __restrict__ ei, int e, int n) {
    int t = blockIdx.x * blockDim.x + threadIdx.x;
    if (t >= e) return;
    int dst = ei[e + t];
    if ((unsigned)dst < (unsigned)n)     // defensive: degrade to rel_err, not IMA
        atomicAdd(&g_deg[dst], 1);
}

// ---------------- K3: single-block exclusive scan of degrees --------------
__global__ void k_scan(int n) {
    __shared__ int s[1024];
    int t = threadIdx.x;
    int chunk = (n + 1023) / 1024;
    int beg = t * chunk;
    int end = beg + chunk; if (end > n) end = n;
    int loc = 0;
    for (int i = beg; i < end; i++) loc += g_deg[i];
    s[t] = loc;
    __syncthreads();
    // Hillis–Steele inclusive scan over 1024 thread-sums
    for (int d = 1; d < 1024; d <<= 1) {
        int v = (t >= d) ? s[t - d] : 0;
        __syncthreads();
        s[t] += v;
        __syncthreads();
    }
    int run = s[t] - loc;  // exclusive prefix for this thread's chunk
    for (int i = beg; i < end; i++) {
        g_off[i] = run;
        g_cur[i] = run;
        run += g_deg[i];
    }
}

// ---------------- K4: scatter edges into CSR by dst -----------------------
__global__ void k_scatter(const int* __restrict__ ei, int e, int n) {
    int t = blockIdx.x * blockDim.x + threadIdx.x;
    if (t >= e) return;
    int src = ei[t];
    int dst = ei[e + t];
    if ((unsigned)dst >= (unsigned)n || (unsigned)src >= (unsigned)n) return;
    int p = atomicAdd(&g_cur[dst], 1);
    g_srt[p] = src;
}

// ---------------- K5: layer0 GEMMs (h0@W0, h0@Wr0) + attention logits -----
// grid = N blocks, 256 threads; thread j = (head j>>5, feat j&31)
__global__ void k_l0_gemm(const float* __restrict__ W0, const float* __restrict__ Wr0,
                          const float* __restrict__ br0, const float* __restrict__ as0,
                          const float* __restrict__ ad0) {
    int i = blockIdx.x;
    int j = threadIdx.x;
    __shared__ float sh[HID];
    if (j < HID) sh[j] = g_h0[i * HID + j];
    __syncthreads();
    float hf = 0.f, rs = 0.f;
#pragma unroll
    for (int k = 0; k < HID; k++) {
        float hk = sh[k];
        hf = fmaf(hk, W0[k * F0 + j], hf);
        rs = fmaf(hk, Wr0[k * F0 + j], rs);
    }
    g_hf0[i * F0 + j] = hf;
    g_res0[i * F0 + j] = rs + br0[j];
    float as = hf * as0[j];
    float ad = hf * ad0[j];
#pragma unroll
    for (int o = 16; o > 0; o >>= 1) {
        as += __shfl_down_sync(FULL, as, o);
        ad += __shfl_down_sync(FULL, ad, o);
    }
    if ((j & 31) == 0) {
        int h = j >> 5;
        g_as0[i * HEADS + h] = as;
        g_ad0[i * HEADS + h] = ad;
    }
}

__device__ __forceinline__ float att_w(float e) {
    e = (e > 0.f) ? e : NEG_SLOPE * e;   // leaky_relu
    return __expf(e);                    // no max-shift needed (logits O(1))
}

// ---------------- K6: layer0 aggregation + bias + ELU + residual + LN -----
// grid = N blocks, 256 threads; warp = head, lane = feature
__global__ void k_l0_agg(const float* __restrict__ bg0, const float* __restrict__ g0,
                         const float* __restrict__ b0) {
    int i = blockIdx.x;
    int tid = threadIdx.x;
    int h = tid >> 5, f = tid & 31;
    float ad = g_ad0[i * HEADS + h];

    // self loop
    float w = att_w(g_as0[i * HEADS + h] + ad);
    float acc = w * g_hf0[i * F0 + tid];
    float den = w;

    int beg = g_off[i];
    int cnt = g_deg[i];
    for (int q = 0; q < cnt; q++) {
        int s = g_srt[beg + q];
        float ww = att_w(g_as0[s * HEADS + h] + ad);
        acc = fmaf(ww, g_hf0[s * F0 + tid], acc);
        den += ww;
    }
    float o = acc / (den + 1e-16f) + bg0[tid];
    o = (o > 0.f) ? o : expm1f(o);       // ELU (alpha=1)
    float v = o + g_res0[i * F0 + tid];

    // block LayerNorm over 256 (two-pass for stability)
    __shared__ float red[8];
    float s1 = v;
#pragma unroll
    for (int off = 16; off > 0; off >>= 1) s1 += __shfl_down_sync(FULL, s1, off);
    if (f == 0) red[h] = s1;
    __syncthreads();
    float tot = 0.f;
#pragma unroll
    for (int u = 0; u < 8; u++) tot += red[u];
    float m = tot * (1.f / F0);
    float d = v - m;
    __syncthreads();
    float s2 = d * d;
#pragma unroll
    for (int off = 16; off > 0; off >>= 1) s2 += __shfl_down_sync(FULL, s2, off);
    if (f == 0) red[h] = s2;
    __syncthreads();
    float vtot = 0.f;
#pragma unroll
    for (int u = 0; u < 8; u++) vtot += red[u];
    float var = vtot * (1.f / F0);

    g_h1[i * F0 + tid] = d * rsqrtf(var + LN_EPS) * g0[tid] + b0[tid];
}

// ---------------- K7: layer1 GEMMs (h1@W1, h1@Wr1) + logits ---------------
// warp per node; lane = output column
__global__ void k_l1_gemm(const float* __restrict__ W1, const float* __restrict__ Wr1,
                          const float* __restrict__ br1, const float* __restrict__ as1,
                          const float* __restrict__ ad1, int n) {
    int warp = (blockIdx.x * blockDim.x + threadIdx.x) >> 5;
    if (warp >= n) return;
    int lane = threadIdx.x & 31;
    const float* row = g_h1 + (size_t)warp * F0;
    float r[8];
#pragma unroll
    for (int u = 0; u < 8; u++) r[u] = row[u * 32 + lane];
    float aw = 0.f, ar = 0.f;
#pragma unroll
    for (int u = 0; u < 8; u++) {
#pragma unroll
        for (int k2 = 0; k2 < 32; k2++) {
            float hk = __shfl_sync(FULL, r[u], k2);
            int k = u * 32 + k2;
            aw = fmaf(hk, W1[k * 32 + lane], aw);
            ar = fmaf(hk, Wr1[k * 32 + lane], ar);
        }
    }
    g_hf1[warp * 32 + lane] = aw;
    g_res1[warp * 32 + lane] = ar + br1[lane];
    float as = aw * as1[lane];
    float ad = aw * ad1[lane];
#pragma unroll
    for (int o = 16; o > 0; o >>= 1) {
        as += __shfl_down_sync(FULL, as, o);
        ad += __shfl_down_sync(FULL, ad, o);
    }
    if (lane == 0) { g_as1[warp] = as; g_ad1[warp] = ad; }
}

// ---------------- K8: layer1 aggregation + residual + LN + partial pool ---
// warp per node; 8 nodes per block; block writes one 32-float partial
__global__ void k_l1_agg(const float* __restrict__ bg1, const float* __restrict__ g1,
                         const float* __restrict__ b1, int n) {
    int tid = threadIdx.x;
    int wid = tid >> 5, lane = tid & 31;
    int i = blockIdx.x * 8 + wid;
    float hfinal = 0.f;
    if (i < n) {
        float ad = g_ad1[i];
        float w = att_w(g_as1[i] + ad);
        float acc = w * g_hf1[i * 32 + lane];
        float den = w;
        int beg = g_off[i];
        int cnt = g_deg[i];
        for (int q = 0; q < cnt; q++) {
            int s = g_srt[beg + q];
            float ww = att_w(g_as1[s] + ad);
            acc = fmaf(ww, g_hf1[s * 32 + lane], acc);
            den += ww;
        }
        float v = acc / (den + 1e-16f) + bg1[lane] + g_res1[i * 32 + lane];
        // warp LayerNorm over 32
        float s1 = v;
#pragma unroll
        for (int o = 16; o > 0; o >>= 1) s1 += __shfl_xor_sync(FULL, s1, o);
        float m = s1 * (1.f / 32.f);
        float d = v - m;
        float s2 = d * d;
#pragma unroll
        for (int o = 16; o > 0; o >>= 1) s2 += __shfl_xor_sync(FULL, s2, o);
        float var = s2 * (1.f / 32.f);
        hfinal = d * rsqrtf(var + LN_EPS) * g1[lane] + b1[lane];
    }
    __shared__ float sp[8][32];
    sp[wid][lane] = hfinal;
    __syncthreads();
    if (wid == 0) {
        float t = 0.f;
#pragma unroll
        for (int u = 0; u < 8; u++) t += sp[u][lane];
        g_part[blockIdx.x * 32 + lane] = t;
    }
}

// ---------------- K9: reduce partials to pooled sum ------------------------
__global__ void k_pool(int nb) {
    int tid = threadIdx.x;
    int f = tid & 31, r0 = tid >> 5;
    float s = 0.f;
    for (int b = r0; b < nb; b += 8) s += g_part[b * 32 + f];
    __shared__ float sh[256];
    sh[tid] = s;
    __syncthreads();
    if (tid < 32) {
        float t = 0.f;
#pragma unroll
        for (int u = 0; u < 8; u++) t += sh[u * 32 + tid];
        g_pool[tid] = t;
    }
}

// ---------------- K10: mean-pool scale + output linear ---------------------
__global__ void k_out(const float* __restrict__ Wout, const float* __restrict__ bout,
                      float* __restrict__ out, int n) {
    int j = threadIdx.x;
    if (j >= OUT_DIM) return;
    float inv = 1.f / (float)n;
    float a = bout[j];
#pragma unroll
    for (int f = 0; f < HID; f++) a = fmaf(g_pool[f] * inv, Wout[f * OUT_DIM + j], a);
    out[j] = a;
}

// ---------------- launch ----------------------------------------------------
extern "C" void kernel_launch(void* const* d_in, const int* in_sizes, int n_in,
                              void* d_out, int out_size) {
    const float* x    = (const float*)d_in[0];
    const int*   ei   = (const int*)d_in[1];   // int64 narrowed to int32 by harness
    // d_in[2] = batch (all zeros) — unused, single graph
    const float* Win  = (const float*)d_in[3];
    const float* bin  = (const float*)d_in[4];
    const float* Wr0  = (const float*)d_in[5];
    const float* br0  = (const float*)d_in[6];
    const float* W0   = (const float*)d_in[7];
    const float* as0  = (const float*)d_in[8];
    const float* ad0  = (const float*)d_in[9];
    const float* bg0  = (const float*)d_in[10];
    const float* g0   = (const float*)d_in[11];
    const float* b0   = (const float*)d_in[12];
    const float* Wr1  = (const float*)d_in[13];
    const float* br1  = (const float*)d_in[14];
    const float* W1   = (const float*)d_in[15];
    const float* as1  = (const float*)d_in[16];
    const float* ad1  = (const float*)d_in[17];
    const float* bg1  = (const float*)d_in[18];
    const float* g1   = (const float*)d_in[19];
    const float* b1   = (const float*)d_in[20];
    const float* Wout = (const float*)d_in[21];
    const float* bout = (const float*)d_in[22];

    int n = in_sizes[0];        // x is [N,1]
    int e = in_sizes[1] / 2;    // edge_index is [2,E]
    int nb = (n + 7) / 8;

    k_in     <<<(n * HID + 255) / 256, 256>>>(x, Win, bin, n);
    k_hist   <<<(e + 255) / 256, 256>>>(ei, e, n);
    k_scan   <<<1, 1024>>>(n);
    k_scatter<<<(e + 255) / 256, 256>>>(ei, e, n);
    k_l0_gemm<<<n, 256>>>(W0, Wr0, br0, as0, ad0);
    k_l0_agg <<<n, 256>>>(bg0, g0, b0);
    k_l1_gemm<<<(n * 32 + 255) / 256, 256>>>(W1, Wr1, br1, as1, ad1, n);
    k_l1_agg <<<nb, 256>>>(bg1, g1, b1, n);
    k_pool   <<<1, 256>>>(nb);
    k_out    <<<1, 32>>>(Wout, bout, (float*)d_out, n);
}

// round 10
// speedup vs baseline: 1.2897x; 1.2897x over previous
#include <cuda_runtime.h>

// Problem constants (match reference setup_inputs)
#define N_NODES 50000
#define N_EDGES 800000
#define HID 32
#define HEADS 8
#define F0 (HID * HEADS)   // 256
#define OUT_DIM 16
#define NEG_SLOPE 0.2f
#define LN_EPS 1e-5f
#define PMAX ((N_NODES + 7) / 8)
#define FULL 0xffffffffu
#define NB1 ((N_NODES + 1023) / 1024)   // scan blocks (49)

// ---------------- static device scratch -----------------------------------
__device__ float g_h0[N_NODES * HID];     // after in_layer (32-wide)
__device__ float g_h1[N_NODES * F0];      // layer0 output (post LN)
__device__ float g_as0[N_NODES * HEADS];  // layer0 src logits
__device__ float g_ad0[N_NODES * HEADS];  // layer0 dst logits
__device__ float g_hf1[N_NODES * HID];    // h1 @ W1
__device__ float g_res1[N_NODES * HID];   // h1 @ Wr1 + br1
__device__ float g_as1[N_NODES];
__device__ float g_ad1[N_NODES];
__device__ float g_P[HID * 16];           // [k][j]: j<8 -> W0_h^T as0_h, j>=8 -> W0_h^T ad0_h
__device__ int   g_deg[N_NODES];
__device__ int   g_off[N_NODES];
__device__ int   g_cur[N_NODES];
__device__ int   g_exc[N_NODES];          // per-element exclusive scan within block
__device__ int   g_bsum[64];              // per-block sums -> exclusive offsets
__device__ int   g_srt[N_EDGES];          // edge src grouped by dst (CSR)
__device__ float g_part[PMAX * HID];      // pooling partials
__device__ float g_pool[HID];

__device__ __forceinline__ float att_w(float e) {
    e = (e > 0.f) ? e : NEG_SLOPE * e;   // leaky_relu
    return __expf(e);                    // logits O(1): no max-shift needed
}

// ---------------- K1: in_layer + zero degree ------------------------------
__global__ void k_in(const float* __restrict__ x, const float* __restrict__ Win,
                     const float* __restrict__ bin, int n) {
    int idx = blockIdx.x * blockDim.x + threadIdx.x;
    if (idx >= n * HID) return;
    int i = idx >> 5, j = idx & 31;
    g_h0[idx] = fmaf(x[i], Win[j], bin[j]);
    if (j == 0) g_deg[i] = 0;
}

// ---------------- K2: histogram of dst (edge_index is int32) --------------
__global__ void k_hist(const int* __restrict__ ei, int e, int n) {
    int t = blockIdx.x * blockDim.x + threadIdx.x;
    if (t >= e) return;
    int dst = ei[e + t];
    if ((unsigned)dst < (unsigned)n)
        atomicAdd(&g_deg[dst], 1);
}

// ---------------- K3a/b/c: coalesced 3-phase exclusive scan ---------------
__global__ void k_scan1(int n) {
    __shared__ int s[1024];
    int t = blockIdx.x * 1024 + threadIdx.x;
    int d = (t < n) ? g_deg[t] : 0;
    s[threadIdx.x] = d;
    __syncthreads();
    for (int o = 1; o < 1024; o <<= 1) {
        int v = (threadIdx.x >= o) ? s[threadIdx.x - o] : 0;
        __syncthreads();
        s[threadIdx.x] += v;
        __syncthreads();
    }
    if (t < n) g_exc[t] = s[threadIdx.x] - d;
    if (threadIdx.x == 1023) g_bsum[blockIdx.x] = s[1023];
}
__global__ void k_scan2(int nb) {
    __shared__ int s[64];
    int t = threadIdx.x;
    int d = (t < nb) ? g_bsum[t] : 0;
    s[t] = d;
    __syncthreads();
    for (int o = 1; o < 64; o <<= 1) {
        int v = (t >= o) ? s[t - o] : 0;
        __syncthreads();
        s[t] += v;
        __syncthreads();
    }
    if (t < nb) g_bsum[t] = s[t] - d;   // exclusive block offsets
}
__global__ void k_scan3(int n) {
    int t = blockIdx.x * blockDim.x + threadIdx.x;
    if (t >= n) return;
    int off = g_exc[t] + g_bsum[t >> 10];
    g_off[t] = off;
    g_cur[t] = off;
}

// ---------------- K4: scatter edges into CSR by dst -----------------------
__global__ void k_scatter(const int* __restrict__ ei, int e, int n) {
    int t = blockIdx.x * blockDim.x + threadIdx.x;
    if (t >= e) return;
    int src = ei[t];
    int dst = ei[e + t];
    if ((unsigned)dst >= (unsigned)n || (unsigned)src >= (unsigned)n) return;
    int p = atomicAdd(&g_cur[dst], 1);
    g_srt[p] = src;
}

// ---------------- K5: projected attention vectors P = W0_h^T {as,ad} ------
// 1 block, 512 threads: thread = (k, j); j<8 -> src vec of head j, j>=8 -> dst vec
__global__ void k_prep(const float* __restrict__ W0, const float* __restrict__ as0,
                       const float* __restrict__ ad0) {
    int t = threadIdx.x;
    int k = t >> 4, j = t & 15;
    int h = (j < 8) ? j : j - 8;
    const float* a = (j < 8) ? (as0 + h * HID) : (ad0 + h * HID);
    float acc = 0.f;
#pragma unroll
    for (int f = 0; f < HID; f++)
        acc = fmaf(W0[k * F0 + h * HID + f], a[f], acc);
    g_P[k * 16 + j] = acc;
}

// ---------------- K6: layer0 logits a_s/a_d = h0 . P ----------------------
// grid = ceil(n/8), 256 threads; warp = node, lanes 0..15 compute outputs
__global__ void k_logits0(int n) {
    __shared__ float sh[8][HID];
    int nl = threadIdx.x >> 5, lane = threadIdx.x & 31;
    int node = blockIdx.x * 8 + nl;
    sh[nl][lane] = (node < n) ? g_h0[node * HID + lane] : 0.f;
    __syncwarp();
    if (node < n && lane < 16) {
        float acc = 0.f;
#pragma unroll
        for (int k = 0; k < HID; k++)
            acc = fmaf(sh[nl][k], g_P[k * 16 + lane], acc);
        if (lane < 8) g_as0[node * 8 + lane] = acc;
        else          g_ad0[node * 8 + lane - 8] = acc;
    }
}

// ---------------- K7: fused layer0 agg(h0) + GEMM + residual + ELU + LN ---
// GAT linearity: sum_e alpha_e (h0 W0) = (sum_e alpha_e h0) W0 per head.
// grid = N blocks, 256 threads; warp = head h, lane = feat f
__global__ void k_l0_fused(const float* __restrict__ W0, const float* __restrict__ Wr0,
                           const float* __restrict__ br0, const float* __restrict__ bg0,
                           const float* __restrict__ g0, const float* __restrict__ b0) {
    int i = blockIdx.x;
    int tid = threadIdx.x, h = tid >> 5, f = tid & 31;
    __shared__ float sh0[HID];        // h0 of dst
    __shared__ float sad[HEADS];      // a_d of dst, all heads
    __shared__ int   ssrc[32];
    __shared__ float sww[32 * HEADS]; // per (edge, head) attention weight
    __shared__ float sagg[F0];
    __shared__ float red[HEADS];
    if (tid < HID)   sh0[tid] = g_h0[i * HID + tid];
    if (tid < HEADS) sad[tid] = g_ad0[i * HEADS + tid];
    __syncthreads();

    float adh = sad[h];
    float w = att_w(g_as0[i * HEADS + h] + adh);     // self loop
    float acc = w * sh0[f];
    float den = w;

    int beg = g_off[i], cnt = g_deg[i];
    for (int c0 = 0; c0 < cnt; c0 += 32) {
        int m = cnt - c0; if (m > 32) m = 32;
        if (tid < 32) ssrc[tid] = (tid < m) ? g_srt[beg + c0 + tid] : -1;
        __syncthreads();
        {   // stage weights: thread (e = tid>>3, hh = tid&7); coalesced 32B as0 reads
            int e = tid >> 3, hh = tid & 7;
            int s = ssrc[e];
            float wv = 0.f;
            if (s >= 0) wv = att_w(g_as0[s * HEADS + hh] + sad[hh]);
            sww[e * HEADS + hh] = wv;
        }
        __syncthreads();
        for (int e = 0; e < m; e++) {
            int s = ssrc[e];                      // smem broadcast
            float ww = sww[e * HEADS + h];        // smem broadcast
            acc = fmaf(ww, g_h0[s * HID + f], acc);  // 128B line, shared by 8 warps
            den += ww;
        }
        __syncthreads();
    }
    sagg[tid] = acc / (den + 1e-16f);
    __syncthreads();

    // per-head 32x32 GEMM (agg @ W0_h) + residual (h0 @ Wr0) — W0/Wr0 L1-resident
    float gat = bg0[tid], res = br0[tid];
#pragma unroll
    for (int k = 0; k < HID; k++) {
        gat = fmaf(sagg[h * HID + k], W0[k * F0 + tid], gat);
        res = fmaf(sh0[k],            Wr0[k * F0 + tid], res);
    }
    gat = (gat > 0.f) ? gat : expm1f(gat);   // ELU
    float v = gat + res;

    // block LayerNorm over 256
    float s1 = v;
#pragma unroll
    for (int o = 16; o > 0; o >>= 1) s1 += __shfl_down_sync(FULL, s1, o);
    if (f == 0) red[h] = s1;
    __syncthreads();
    float tot = 0.f;
#pragma unroll
    for (int u = 0; u < 8; u++) tot += red[u];
    float mn = tot * (1.f / F0);
    float d = v - mn;
    __syncthreads();
    float s2 = d * d;
#pragma unroll
    for (int o = 16; o > 0; o >>= 1) s2 += __shfl_down_sync(FULL, s2, o);
    if (f == 0) red[h] = s2;
    __syncthreads();
    float vtot = 0.f;
#pragma unroll
    for (int u = 0; u < 8; u++) vtot += red[u];
    float var = vtot * (1.f / F0);

    g_h1[i * F0 + tid] = d * rsqrtf(var + LN_EPS) * g0[tid] + b0[tid];
}

// ---------------- K8: layer1 GEMMs (h1@W1, h1@Wr1) + logits ---------------
__global__ void k_l1_gemm(const float* __restrict__ W1, const float* __restrict__ Wr1,
                          const float* __restrict__ br1, const float* __restrict__ as1,
                          const float* __restrict__ ad1, int n) {
    int warp = (blockIdx.x * blockDim.x + threadIdx.x) >> 5;
    if (warp >= n) return;
    int lane = threadIdx.x & 31;
    const float* row = g_h1 + (size_t)warp * F0;
    float r[8];
#pragma unroll
    for (int u = 0; u < 8; u++) r[u] = row[u * 32 + lane];
    float aw = 0.f, ar = 0.f;
#pragma unroll
    for (int u = 0; u < 8; u++) {
#pragma unroll
        for (int k2 = 0; k2 < 32; k2++) {
            float hk = __shfl_sync(FULL, r[u], k2);
            int k = u * 32 + k2;
            aw = fmaf(hk, W1[k * 32 + lane], aw);
            ar = fmaf(hk, Wr1[k * 32 + lane], ar);
        }
    }
    g_hf1[warp * 32 + lane] = aw;
    g_res1[warp * 32 + lane] = ar + br1[lane];
    float as = aw * as1[lane];
    float ad = aw * ad1[lane];
#pragma unroll
    for (int o = 16; o > 0; o >>= 1) {
        as += __shfl_down_sync(FULL, as, o);
        ad += __shfl_down_sync(FULL, ad, o);
    }
    if (lane == 0) { g_as1[warp] = as; g_ad1[warp] = ad; }
}

// ---------------- K9: layer1 agg (chunked shuffle) + LN + partial pool ----
__global__ void k_l1_agg(const float* __restrict__ bg1, const float* __restrict__ g1,
                         const float* __restrict__ b1, int n) {
    int tid = threadIdx.x;
    int wid = tid >> 5, lane = tid & 31;
    int i = blockIdx.x * 8 + wid;
    float hfinal = 0.f;
    if (i < n) {                                     // warp-uniform
        float ad = g_ad1[i];
        float w = att_w(g_as1[i] + ad);
        float acc = w * g_hf1[i * 32 + lane];
        float den = w;
        int beg = g_off[i], cnt = g_deg[i];
        for (int c0 = 0; c0 < cnt; c0 += 32) {
            int r = c0 + lane;
            int sl = 0; float wv = 0.f;
            if (r < cnt) {                           // coalesced srt + weight once/edge
                sl = g_srt[beg + r];
                wv = att_w(g_as1[sl] + ad);
            }
            int m = cnt - c0; if (m > 32) m = 32;
            for (int j = 0; j < m; j++) {
                float wj = __shfl_sync(FULL, wv, j);
                int   sj = __shfl_sync(FULL, sl, j);
                acc = fmaf(wj, g_hf1[sj * 32 + lane], acc);
                den += wj;
            }
        }
        float v = acc / (den + 1e-16f) + bg1[lane] + g_res1[i * 32 + lane];
        float s1 = v;
#pragma unroll
        for (int o = 16; o > 0; o >>= 1) s1 += __shfl_xor_sync(FULL, s1, o);
        float mn = s1 * (1.f / 32.f);
        float d = v - mn;
        float s2 = d * d;
#pragma unroll
        for (int o = 16; o > 0; o >>= 1) s2 += __shfl_xor_sync(FULL, s2, o);
        float var = s2 * (1.f / 32.f);
        hfinal = d * rsqrtf(var + LN_EPS) * g1[lane] + b1[lane];
    }
    __shared__ float sp[8][32];
    sp[wid][lane] = hfinal;
    __syncthreads();
    if (wid == 0) {
        float t = 0.f;
#pragma unroll
        for (int u = 0; u < 8; u++) t += sp[u][lane];
        g_part[blockIdx.x * 32 + lane] = t;
    }
}

// ---------------- K10: reduce partials ------------------------------------
__global__ void k_pool(int nb) {
    int tid = threadIdx.x;
    int f = tid & 31, r0 = tid >> 5;
    float s = 0.f;
    for (int b = r0; b < nb; b += 8) s += g_part[b * 32 + f];
    __shared__ float sh[256];
    sh[tid] = s;
    __syncthreads();
    if (tid < 32) {
        float t = 0.f;
#pragma unroll
        for (int u = 0; u < 8; u++) t += sh[u * 32 + tid];
        g_pool[tid] = t;
    }
}

// ---------------- K11: mean-pool scale + output linear --------------------
__global__ void k_out(const float* __restrict__ Wout, const float* __restrict__ bout,
                      float* __restrict__ out, int n) {
    int j = threadIdx.x;
    if (j >= OUT_DIM) return;
    float inv = 1.f / (float)n;
    float a = bout[j];
#pragma unroll
    for (int f = 0; f < HID; f++) a = fmaf(g_pool[f] * inv, Wout[f * OUT_DIM + j], a);
    out[j] = a;
}

// ---------------- launch ----------------------------------------------------
extern "C" void kernel_launch(void* const* d_in, const int* in_sizes, int n_in,
                              void* d_out, int out_size) {
    const float* x    = (const float*)d_in[0];
    const int*   ei   = (const int*)d_in[1];   // int64 narrowed to int32 by harness
    // d_in[2] = batch (all zeros) — unused, single graph
    const float* Win  = (const float*)d_in[3];
    const float* bin  = (const float*)d_in[4];
    const float* Wr0  = (const float*)d_in[5];
    const float* br0  = (const float*)d_in[6];
    const float* W0   = (const float*)d_in[7];
    const float* as0  = (const float*)d_in[8];
    const float* ad0  = (const float*)d_in[9];
    const float* bg0  = (const float*)d_in[10];
    const float* g0   = (const float*)d_in[11];
    const float* b0   = (const float*)d_in[12];
    const float* Wr1  = (const float*)d_in[13];
    const float* br1  = (const float*)d_in[14];
    const float* W1   = (const float*)d_in[15];
    const float* as1  = (const float*)d_in[16];
    const float* ad1  = (const float*)d_in[17];
    const float* bg1  = (const float*)d_in[18];
    const float* g1   = (const float*)d_in[19];
    const float* b1   = (const float*)d_in[20];
    const float* Wout = (const float*)d_in[21];
    const float* bout = (const float*)d_in[22];

    int n = in_sizes[0];        // x is [N,1]
    int e = in_sizes[1] / 2;    // edge_index is [2,E]
    int nb = (n + 7) / 8;
    int nb1 = (n + 1023) / 1024;

    k_in     <<<(n * HID + 255) / 256, 256>>>(x, Win, bin, n);
    k_hist   <<<(e + 255) / 256, 256>>>(ei, e, n);
    k_scan1  <<<nb1, 1024>>>(n);
    k_scan2  <<<1, 64>>>(nb1);
    k_scan3  <<<(n + 255) / 256, 256>>>(n);
    k_scatter<<<(e + 255) / 256, 256>>>(ei, e, n);
    k_prep   <<<1, 512>>>(W0, as0, ad0);
    k_logits0<<<(n + 7) / 8, 256>>>(n);
    k_l0_fused<<<n, 256>>>(W0, Wr0, br0, bg0, g0, b0);
    k_l1_gemm<<<(n * 32 + 255) / 256, 256>>>(W1, Wr1, br1, as1, ad1, n);
    k_l1_agg <<<nb, 256>>>(bg1, g1, b1, n);
    k_pool   <<<1, 256>>>(nb);
    k_out    <<<1, 32>>>(Wout, bout, (float*)d_out, n);
}

// round 11
// speedup vs baseline: 1.2909x; 1.0009x over previous
#include <cuda_runtime.h>

// Problem constants (match reference setup_inputs)
#define N_NODES 50000
#define N_EDGES 800000
#define HID 32
#define HEADS 8
#define F0 (HID * HEADS)   // 256
#define OUT_DIM 16
#define NEG_SLOPE 0.2f
#define LN_EPS 1e-5f
#define PMAX ((N_NODES + 7) / 8)
#define FULL 0xffffffffu
#define NB1 ((N_NODES + 1023) / 1024)   // scan blocks (49)

// ---------------- static device scratch -----------------------------------
__device__ float g_h0[N_NODES * HID];     // after in_layer (32-wide)
__device__ float g_h1[N_NODES * F0];      // layer0 output (post LN)
__device__ float g_as0[N_NODES * HEADS];  // layer0 src logits
__device__ float g_ad0[N_NODES * HEADS];  // layer0 dst logits
__device__ float g_hf1[N_NODES * HID];    // h1 @ W1
__device__ float g_res1[N_NODES * HID];   // h1 @ Wr1 + br1
__device__ float g_as1[N_NODES];
__device__ float g_ad1[N_NODES];
__device__ float g_P[HID * 16];           // [k][j]: j<8 -> W0_h^T as0_h, j>=8 -> W0_h^T ad0_h
__device__ int   g_deg[N_NODES];
__device__ int   g_off[N_NODES];
__device__ int   g_cur[N_NODES];
__device__ int   g_exc[N_NODES];          // per-element exclusive scan within block
__device__ int   g_bsum[64];              // per-block sums -> exclusive offsets
__device__ int   g_srt[N_EDGES];          // edge src grouped by dst (CSR)
__device__ float g_part[PMAX * HID];      // pooling partials
__device__ float g_pool[HID];

__device__ __forceinline__ float att_w(float e) {
    e = (e > 0.f) ? e : NEG_SLOPE * e;   // leaky_relu
    return __expf(e);                    // logits O(1): no max-shift needed
}

// ---------------- K1: in_layer + zero degree ------------------------------
__global__ void k_in(const float* __restrict__ x, const float* __restrict__ Win,
                     const float* __restrict__ bin, int n) {
    int idx = blockIdx.x * blockDim.x + threadIdx.x;
    if (idx >= n * HID) return;
    int i = idx >> 5, j = idx & 31;
    g_h0[idx] = fmaf(x[i], Win[j], bin[j]);
    if (j == 0) g_deg[i] = 0;
}

// ---------------- K2: histogram of dst (edge_index is int32) --------------
__global__ void k_hist(const int* __restrict__ ei, int e, int n) {
    int t = blockIdx.x * blockDim.x + threadIdx.x;
    if (t >= e) return;
    int dst = ei[e + t];
    if ((unsigned)dst < (unsigned)n)
        atomicAdd(&g_deg[dst], 1);
}

// ---------------- K3a/b/c: coalesced 3-phase exclusive scan ---------------
__global__ void k_scan1(int n) {
    __shared__ int s[1024];
    int t = blockIdx.x * 1024 + threadIdx.x;
    int d = (t < n) ? g_deg[t] : 0;
    s[threadIdx.x] = d;
    __syncthreads();
    for (int o = 1; o < 1024; o <<= 1) {
        int v = (threadIdx.x >= o) ? s[threadIdx.x - o] : 0;
        __syncthreads();
        s[threadIdx.x] += v;
        __syncthreads();
    }
    if (t < n) g_exc[t] = s[threadIdx.x] - d;
    if (threadIdx.x == 1023) g_bsum[blockIdx.x] = s[1023];
}
__global__ void k_scan2(int nb) {
    __shared__ int s[64];
    int t = threadIdx.x;
    int d = (t < nb) ? g_bsum[t] : 0;
    s[t] = d;
    __syncthreads();
    for (int o = 1; o < 64; o <<= 1) {
        int v = (t >= o) ? s[t - o] : 0;
        __syncthreads();
        s[t] += v;
        __syncthreads();
    }
    if (t < nb) g_bsum[t] = s[t] - d;   // exclusive block offsets
}
__global__ void k_scan3(int n) {
    int t = blockIdx.x * blockDim.x + threadIdx.x;
    if (t >= n) return;
    int off = g_exc[t] + g_bsum[t >> 10];
    g_off[t] = off;
    g_cur[t] = off;
}

// ---------------- K4: scatter edges into CSR by dst -----------------------
__global__ void k_scatter(const int* __restrict__ ei, int e, int n) {
    int t = blockIdx.x * blockDim.x + threadIdx.x;
    if (t >= e) return;
    int src = ei[t];
    int dst = ei[e + t];
    if ((unsigned)dst >= (unsigned)n || (unsigned)src >= (unsigned)n) return;
    int p = atomicAdd(&g_cur[dst], 1);
    g_srt[p] = src;
}

// ---------------- K5: projected attention vectors P = W0_h^T {as,ad} ------
// 1 block, 512 threads: thread = (k, j); j<8 -> src vec of head j, j>=8 -> dst vec
__global__ void k_prep(const float* __restrict__ W0, const float* __restrict__ as0,
                       const float* __restrict__ ad0) {
    int t = threadIdx.x;
    int k = t >> 4, j = t & 15;
    int h = (j < 8) ? j : j - 8;
    const float* a = (j < 8) ? (as0 + h * HID) : (ad0 + h * HID);
    float acc = 0.f;
#pragma unroll
    for (int f = 0; f < HID; f++)
        acc = fmaf(W0[k * F0 + h * HID + f], a[f], acc);
    g_P[k * 16 + j] = acc;
}

// ---------------- K6: layer0 logits a_s/a_d = h0 . P ----------------------
// grid = ceil(n/8), 256 threads; warp = node, lanes 0..15 compute outputs
__global__ void k_logits0(int n) {
    __shared__ float sh[8][HID];
    int nl = threadIdx.x >> 5, lane = threadIdx.x & 31;
    int node = blockIdx.x * 8 + nl;
    sh[nl][lane] = (node < n) ? g_h0[node * HID + lane] : 0.f;
    __syncwarp();
    if (node < n && lane < 16) {
        float acc = 0.f;
#pragma unroll
        for (int k = 0; k < HID; k++)
            acc = fmaf(sh[nl][k], g_P[k * 16 + lane], acc);
        if (lane < 8) g_as0[node * 8 + lane] = acc;
        else          g_ad0[node * 8 + lane - 8] = acc;
    }
}

// ---------------- K7: fused layer0 agg(h0) + GEMM + residual + ELU + LN ---
// GAT linearity: sum_e alpha_e (h0 W0) = (sum_e alpha_e h0) W0 per head.
// grid = N blocks, 256 threads; warp = head h, lane = feat f
__global__ void k_l0_fused(const float* __restrict__ W0, const float* __restrict__ Wr0,
                           const float* __restrict__ br0, const float* __restrict__ bg0,
                           const float* __restrict__ g0, const float* __restrict__ b0) {
    int i = blockIdx.x;
    int tid = threadIdx.x, h = tid >> 5, f = tid & 31;
    __shared__ float sh0[HID];        // h0 of dst
    __shared__ float sad[HEADS];      // a_d of dst, all heads
    __shared__ int   ssrc[32];
    __shared__ float sww[32 * HEADS]; // per (edge, head) attention weight
    __shared__ float sagg[F0];
    __shared__ float red[HEADS];
    if (tid < HID)   sh0[tid] = g_h0[i * HID + tid];
    if (tid < HEADS) sad[tid] = g_ad0[i * HEADS + tid];
    __syncthreads();

    float adh = sad[h];
    float w = att_w(g_as0[i * HEADS + h] + adh);     // self loop
    float acc = w * sh0[f];
    float den = w;

    int beg = g_off[i], cnt = g_deg[i];
    for (int c0 = 0; c0 < cnt; c0 += 32) {
        int m = cnt - c0; if (m > 32) m = 32;
        if (tid < 32) ssrc[tid] = (tid < m) ? g_srt[beg + c0 + tid] : -1;
        __syncthreads();
        {   // stage weights: thread (e = tid>>3, hh = tid&7); coalesced 32B as0 reads
            int e = tid >> 3, hh = tid & 7;
            int s = ssrc[e];
            float wv = 0.f;
            if (s >= 0) wv = att_w(g_as0[s * HEADS + hh] + sad[hh]);
            sww[e * HEADS + hh] = wv;
        }
        __syncthreads();
        for (int e = 0; e < m; e++) {
            int s = ssrc[e];                      // smem broadcast
            float ww = sww[e * HEADS + h];        // smem broadcast
            acc = fmaf(ww, g_h0[s * HID + f], acc);  // 128B line, shared by 8 warps
            den += ww;
        }
        __syncthreads();
    }
    sagg[tid] = acc / (den + 1e-16f);
    __syncthreads();

    // per-head 32x32 GEMM (agg @ W0_h) + residual (h0 @ Wr0) — W0/Wr0 L1-resident
    float gat = bg0[tid], res = br0[tid];
#pragma unroll
    for (int k = 0; k < HID; k++) {
        gat = fmaf(sagg[h * HID + k], W0[k * F0 + tid], gat);
        res = fmaf(sh0[k],            Wr0[k * F0 + tid], res);
    }
    gat = (gat > 0.f) ? gat : expm1f(gat);   // ELU
    float v = gat + res;

    // block LayerNorm over 256
    float s1 = v;
#pragma unroll
    for (int o = 16; o > 0; o >>= 1) s1 += __shfl_down_sync(FULL, s1, o);
    if (f == 0) red[h] = s1;
    __syncthreads();
    float tot = 0.f;
#pragma unroll
    for (int u = 0; u < 8; u++) tot += red[u];
    float mn = tot * (1.f / F0);
    float d = v - mn;
    __syncthreads();
    float s2 = d * d;
#pragma unroll
    for (int o = 16; o > 0; o >>= 1) s2 += __shfl_down_sync(FULL, s2, o);
    if (f == 0) red[h] = s2;
    __syncthreads();
    float vtot = 0.f;
#pragma unroll
    for (int u = 0; u < 8; u++) vtot += red[u];
    float var = vtot * (1.f / F0);

    g_h1[i * F0 + tid] = d * rsqrtf(var + LN_EPS) * g0[tid] + b0[tid];
}

// ---------------- K8: layer1 GEMMs (h1@W1, h1@Wr1) + logits ---------------
__global__ void k_l1_gemm(const float* __restrict__ W1, const float* __restrict__ Wr1,
                          const float* __restrict__ br1, const float* __restrict__ as1,
                          const float* __restrict__ ad1, int n) {
    int warp = (blockIdx.x * blockDim.x + threadIdx.x) >> 5;
    if (warp >= n) return;
    int lane = threadIdx.x & 31;
    const float* row = g_h1 + (size_t)warp * F0;
    float r[8];
#pragma unroll
    for (int u = 0; u < 8; u++) r[u] = row[u * 32 + lane];
    float aw = 0.f, ar = 0.f;
#pragma unroll
    for (int u = 0; u < 8; u++) {
#pragma unroll
        for (int k2 = 0; k2 < 32; k2++) {
            float hk = __shfl_sync(FULL, r[u], k2);
            int k = u * 32 + k2;
            aw = fmaf(hk, W1[k * 32 + lane], aw);
            ar = fmaf(hk, Wr1[k * 32 + lane], ar);
        }
    }
    g_hf1[warp * 32 + lane] = aw;
    g_res1[warp * 32 + lane] = ar + br1[lane];
    float as = aw * as1[lane];
    float ad = aw * ad1[lane];
#pragma unroll
    for (int o = 16; o > 0; o >>= 1) {
        as += __shfl_down_sync(FULL, as, o);
        ad += __shfl_down_sync(FULL, ad, o);
    }
    if (lane == 0) { g_as1[warp] = as; g_ad1[warp] = ad; }
}

// ---------------- K9: layer1 agg (chunked shuffle) + LN + partial pool ----
__global__ void k_l1_agg(const float* __restrict__ bg1, const float* __restrict__ g1,
                         const float* __restrict__ b1, int n) {
    int tid = threadIdx.x;
    int wid = tid >> 5, lane = tid & 31;
    int i = blockIdx.x * 8 + wid;
    float hfinal = 0.f;
    if (i < n) {                                     // warp-uniform
        float ad = g_ad1[i];
        float w = att_w(g_as1[i] + ad);
        float acc = w * g_hf1[i * 32 + lane];
        float den = w;
        int beg = g_off[i], cnt = g_deg[i];
        for (int c0 = 0; c0 < cnt; c0 += 32) {
            int r = c0 + lane;
            int sl = 0; float wv = 0.f;
            if (r < cnt) {                           // coalesced srt + weight once/edge
                sl = g_srt[beg + r];
                wv = att_w(g_as1[sl] + ad);
            }
            int m = cnt - c0; if (m > 32) m = 32;
            for (int j = 0; j < m; j++) {
                float wj = __shfl_sync(FULL, wv, j);
                int   sj = __shfl_sync(FULL, sl, j);
                acc = fmaf(wj, g_hf1[sj * 32 + lane], acc);
                den += wj;
            }
        }
        float v = acc / (den + 1e-16f) + bg1[lane] + g_res1[i * 32 + lane];
        float s1 = v;
#pragma unroll
        for (int o = 16; o > 0; o >>= 1) s1 += __shfl_xor_sync(FULL, s1, o);
        float mn = s1 * (1.f / 32.f);
        float d = v - mn;
        float s2 = d * d;
#pragma unroll
        for (int o = 16; o > 0; o >>= 1) s2 += __shfl_xor_sync(FULL, s2, o);
        float var = s2 * (1.f / 32.f);
        hfinal = d * rsqrtf(var + LN_EPS) * g1[lane] + b1[lane];
    }
    __shared__ float sp[8][32];
    sp[wid][lane] = hfinal;
    __syncthreads();
    if (wid == 0) {
        float t = 0.f;
#pragma unroll
        for (int u = 0; u < 8; u++) t += sp[u][lane];
        g_part[blockIdx.x * 32 + lane] = t;
    }
}

// ---------------- K10: reduce partials ------------------------------------
__global__ void k_pool(int nb) {
    int tid = threadIdx.x;
    int f = tid & 31, r0 = tid >> 5;
    float s = 0.f;
    for (int b = r0; b < nb; b += 8) s += g_part[b * 32 + f];
    __shared__ float sh[256];
    sh[tid] = s;
    __syncthreads();
    if (tid < 32) {
        float t = 0.f;
#pragma unroll
        for (int u = 0; u < 8; u++) t += sh[u * 32 + tid];
        g_pool[tid] = t;
    }
}

// ---------------- K11: mean-pool scale + output linear --------------------
__global__ void k_out(const float* __restrict__ Wout, const float* __restrict__ bout,
                      float* __restrict__ out, int n) {
    int j = threadIdx.x;
    if (j >= OUT_DIM) return;
    float inv = 1.f / (float)n;
    float a = bout[j];
#pragma unroll
    for (int f = 0; f < HID; f++) a = fmaf(g_pool[f] * inv, Wout[f * OUT_DIM + j], a);
    out[j] = a;
}

// ---------------- launch ----------------------------------------------------
extern "C" void kernel_launch(void* const* d_in, const int* in_sizes, int n_in,
                              void* d_out, int out_size) {
    const float* x    = (const float*)d_in[0];
    const int*   ei   = (const int*)d_in[1];   // int64 narrowed to int32 by harness
    // d_in[2] = batch (all zeros) — unused, single graph
    const float* Win  = (const float*)d_in[3];
    const float* bin  = (const float*)d_in[4];
    const float* Wr0  = (const float*)d_in[5];
    const float* br0  = (const float*)d_in[6];
    const float* W0   = (const float*)d_in[7];
    const float* as0  = (const float*)d_in[8];
    const float* ad0  = (const float*)d_in[9];
    const float* bg0  = (const float*)d_in[10];
    const float* g0   = (const float*)d_in[11];
    const float* b0   = (const float*)d_in[12];
    const float* Wr1  = (const float*)d_in[13];
    const float* br1  = (const float*)d_in[14];
    const float* W1   = (const float*)d_in[15];
    const float* as1  = (const float*)d_in[16];
    const float* ad1  = (const float*)d_in[17];
    const float* bg1  = (const float*)d_in[18];
    const float* g1   = (const float*)d_in[19];
    const float* b1   = (const float*)d_in[20];
    const float* Wout = (const float*)d_in[21];
    const float* bout = (const float*)d_in[22];

    int n = in_sizes[0];        // x is [N,1]
    int e = in_sizes[1] / 2;    // edge_index is [2,E]
    int nb = (n + 7) / 8;
    int nb1 = (n + 1023) / 1024;

    k_in     <<<(n * HID + 255) / 256, 256>>>(x, Win, bin, n);
    k_hist   <<<(e + 255) / 256, 256>>>(ei, e, n);
    k_scan1  <<<nb1, 1024>>>(n);
    k_scan2  <<<1, 64>>>(nb1);
    k_scan3  <<<(n + 255) / 256, 256>>>(n);
    k_scatter<<<(e + 255) / 256, 256>>>(ei, e, n);
    k_prep   <<<1, 512>>>(W0, as0, ad0);
    k_logits0<<<(n + 7) / 8, 256>>>(n);
    k_l0_fused<<<n, 256>>>(W0, Wr0, br0, bg0, g0, b0);
    k_l1_gemm<<<(n * 32 + 255) / 256, 256>>>(W1, Wr1, br1, as1, ad1, n);
    k_l1_agg <<<nb, 256>>>(bg1, g1, b1, n);
    k_pool   <<<1, 256>>>(nb);
    k_out    <<<1, 32>>>(Wout, bout, (float*)d_out, n);
}

// round 12
// speedup vs baseline: 1.2927x; 1.0014x over previous
#include <cuda_runtime.h>

// Problem constants (match reference setup_inputs)
#define N_NODES 50000
#define N_EDGES 800000
#define HID 32
#define HEADS 8
#define F0 (HID * HEADS)   // 256
#define OUT_DIM 16
#define NEG_SLOPE 0.2f
#define LN_EPS 1e-5f
#define PMAX ((N_NODES + 7) / 8)
#define FULL 0xffffffffu
#define NB1 ((N_NODES + 1023) / 1024)   // scan blocks (49)

// ---------------- static device scratch -----------------------------------
__device__ float g_h0[N_NODES * HID];     // after in_layer (32-wide)
__device__ float g_h1[N_NODES * F0];      // layer0 output (post LN)
__device__ float g_as0[N_NODES * HEADS];  // layer0 src logits
__device__ float g_ad0[N_NODES * HEADS];  // layer0 dst logits
__device__ float g_hf1[N_NODES * HID];    // h1 @ W1
__device__ float g_res1[N_NODES * HID];   // h1 @ Wr1 + br1
__device__ float g_as1[N_NODES];
__device__ float g_ad1[N_NODES];
__device__ float g_P[HID * 16];           // [k][j]: j<8 -> W0_h^T as0_h, j>=8 -> W0_h^T ad0_h
__device__ int   g_deg[N_NODES];
__device__ int   g_off[N_NODES];
__device__ int   g_cur[N_NODES];
__device__ int   g_exc[N_NODES];          // per-element exclusive scan within block
__device__ int   g_bsum[64];              // per-block sums -> exclusive offsets
__device__ int   g_srt[N_EDGES];          // edge src grouped by dst (CSR)
__device__ float g_part[PMAX * HID];      // pooling partials
__device__ float g_pool[HID];

__device__ __forceinline__ float att_w(float e) {
    e = (e > 0.f) ? e : NEG_SLOPE * e;   // leaky_relu
    return __expf(e);                    // logits O(1): no max-shift needed
}

// ---------------- K1: in_layer + zero degree ------------------------------
__global__ void k_in(const float* __restrict__ x, const float* __restrict__ Win,
                     const float* __restrict__ bin, int n) {
    int idx = blockIdx.x * blockDim.x + threadIdx.x;
    if (idx >= n * HID) return;
    int i = idx >> 5, j = idx & 31;
    g_h0[idx] = fmaf(x[i], Win[j], bin[j]);
    if (j == 0) g_deg[i] = 0;
}

// ---------------- K2: histogram of dst (edge_index is int32) --------------
__global__ void k_hist(const int* __restrict__ ei, int e, int n) {
    int t = blockIdx.x * blockDim.x + threadIdx.x;
    if (t >= e) return;
    int dst = ei[e + t];
    if ((unsigned)dst < (unsigned)n)
        atomicAdd(&g_deg[dst], 1);
}

// ---------------- K3a/b/c: coalesced 3-phase exclusive scan ---------------
__global__ void k_scan1(int n) {
    __shared__ int s[1024];
    int t = blockIdx.x * 1024 + threadIdx.x;
    int d = (t < n) ? g_deg[t] : 0;
    s[threadIdx.x] = d;
    __syncthreads();
    for (int o = 1; o < 1024; o <<= 1) {
        int v = (threadIdx.x >= o) ? s[threadIdx.x - o] : 0;
        __syncthreads();
        s[threadIdx.x] += v;
        __syncthreads();
    }
    if (t < n) g_exc[t] = s[threadIdx.x] - d;
    if (threadIdx.x == 1023) g_bsum[blockIdx.x] = s[1023];
}
__global__ void k_scan2(int nb) {
    __shared__ int s[64];
    int t = threadIdx.x;
    int d = (t < nb) ? g_bsum[t] : 0;
    s[t] = d;
    __syncthreads();
    for (int o = 1; o < 64; o <<= 1) {
        int v = (t >= o) ? s[t - o] : 0;
        __syncthreads();
        s[t] += v;
        __syncthreads();
    }
    if (t < nb) g_bsum[t] = s[t] - d;   // exclusive block offsets
}
__global__ void k_scan3(int n) {
    int t = blockIdx.x * blockDim.x + threadIdx.x;
    if (t >= n) return;
    int off = g_exc[t] + g_bsum[t >> 10];
    g_off[t] = off;
    g_cur[t] = off;
}

// ---------------- K4: scatter edges into CSR by dst -----------------------
__global__ void k_scatter(const int* __restrict__ ei, int e, int n) {
    int t = blockIdx.x * blockDim.x + threadIdx.x;
    if (t >= e) return;
    int src = ei[t];
    int dst = ei[e + t];
    if ((unsigned)dst >= (unsigned)n || (unsigned)src >= (unsigned)n) return;
    int p = atomicAdd(&g_cur[dst], 1);
    g_srt[p] = src;
}

// ---------------- K5: projected attention vectors P = W0_h^T {as,ad} ------
// 1 block, 512 threads: thread = (k, j); j<8 -> src vec of head j, j>=8 -> dst vec
__global__ void k_prep(const float* __restrict__ W0, const float* __restrict__ as0,
                       const float* __restrict__ ad0) {
    int t = threadIdx.x;
    int k = t >> 4, j = t & 15;
    int h = (j < 8) ? j : j - 8;
    const float* a = (j < 8) ? (as0 + h * HID) : (ad0 + h * HID);
    float acc = 0.f;
#pragma unroll
    for (int f = 0; f < HID; f++)
        acc = fmaf(W0[k * F0 + h * HID + f], a[f], acc);
    g_P[k * 16 + j] = acc;
}

// ---------------- K6: layer0 logits a_s/a_d = h0 . P ----------------------
// grid = ceil(n/8), 256 threads; warp = node, lanes 0..15 compute outputs
__global__ void k_logits0(int n) {
    __shared__ float sh[8][HID];
    int nl = threadIdx.x >> 5, lane = threadIdx.x & 31;
    int node = blockIdx.x * 8 + nl;
    sh[nl][lane] = (node < n) ? g_h0[node * HID + lane] : 0.f;
    __syncwarp();
    if (node < n && lane < 16) {
        float acc = 0.f;
#pragma unroll
        for (int k = 0; k < HID; k++)
            acc = fmaf(sh[nl][k], g_P[k * 16 + lane], acc);
        if (lane < 8) g_as0[node * 8 + lane] = acc;
        else          g_ad0[node * 8 + lane - 8] = acc;
    }
}

// ---------------- K7: fused layer0 agg(h0) + GEMM + residual + ELU + LN ---
// GAT linearity: sum_e alpha_e (h0 W0) = (sum_e alpha_e h0) W0 per head.
// grid = N blocks, 256 threads; warp = head h, lane = feat f
__global__ void k_l0_fused(const float* __restrict__ W0, const float* __restrict__ Wr0,
                           const float* __restrict__ br0, const float* __restrict__ bg0,
                           const float* __restrict__ g0, const float* __restrict__ b0) {
    int i = blockIdx.x;
    int tid = threadIdx.x, h = tid >> 5, f = tid & 31;
    __shared__ float sh0[HID];        // h0 of dst
    __shared__ float sad[HEADS];      // a_d of dst, all heads
    __shared__ int   ssrc[32];
    __shared__ float sww[32 * HEADS]; // per (edge, head) attention weight
    __shared__ float sagg[F0];
    __shared__ float red[HEADS];
    if (tid < HID)   sh0[tid] = g_h0[i * HID + tid];
    if (tid < HEADS) sad[tid] = g_ad0[i * HEADS + tid];
    __syncthreads();

    float adh = sad[h];
    float w = att_w(g_as0[i * HEADS + h] + adh);     // self loop
    float acc = w * sh0[f];
    float den = w;

    int beg = g_off[i], cnt = g_deg[i];
    for (int c0 = 0; c0 < cnt; c0 += 32) {
        int m = cnt - c0; if (m > 32) m = 32;
        if (tid < 32) ssrc[tid] = (tid < m) ? g_srt[beg + c0 + tid] : -1;
        __syncthreads();
        {   // stage weights: thread (e = tid>>3, hh = tid&7); coalesced 32B as0 reads
            int e = tid >> 3, hh = tid & 7;
            int s = ssrc[e];
            float wv = 0.f;
            if (s >= 0) wv = att_w(g_as0[s * HEADS + hh] + sad[hh]);
            sww[e * HEADS + hh] = wv;
        }
        __syncthreads();
        for (int e = 0; e < m; e++) {
            int s = ssrc[e];                      // smem broadcast
            float ww = sww[e * HEADS + h];        // smem broadcast
            acc = fmaf(ww, g_h0[s * HID + f], acc);  // 128B line, shared by 8 warps
            den += ww;
        }
        __syncthreads();
    }
    sagg[tid] = acc / (den + 1e-16f);
    __syncthreads();

    // per-head 32x32 GEMM (agg @ W0_h) + residual (h0 @ Wr0) — W0/Wr0 L1-resident
    float gat = bg0[tid], res = br0[tid];
#pragma unroll
    for (int k = 0; k < HID; k++) {
        gat = fmaf(sagg[h * HID + k], W0[k * F0 + tid], gat);
        res = fmaf(sh0[k],            Wr0[k * F0 + tid], res);
    }
    gat = (gat > 0.f) ? gat : expm1f(gat);   // ELU
    float v = gat + res;

    // block LayerNorm over 256
    float s1 = v;
#pragma unroll
    for (int o = 16; o > 0; o >>= 1) s1 += __shfl_down_sync(FULL, s1, o);
    if (f == 0) red[h] = s1;
    __syncthreads();
    float tot = 0.f;
#pragma unroll
    for (int u = 0; u < 8; u++) tot += red[u];
    float mn = tot * (1.f / F0);
    float d = v - mn;
    __syncthreads();
    float s2 = d * d;
#pragma unroll
    for (int o = 16; o > 0; o >>= 1) s2 += __shfl_down_sync(FULL, s2, o);
    if (f == 0) red[h] = s2;
    __syncthreads();
    float vtot = 0.f;
#pragma unroll
    for (int u = 0; u < 8; u++) vtot += red[u];
    float var = vtot * (1.f / F0);

    g_h1[i * F0 + tid] = d * rsqrtf(var + LN_EPS) * g0[tid] + b0[tid];
}

// ---------------- K8: layer1 GEMMs (h1@W1, h1@Wr1) + logits ---------------
__global__ void k_l1_gemm(const float* __restrict__ W1, const float* __restrict__ Wr1,
                          const float* __restrict__ br1, const float* __restrict__ as1,
                          const float* __restrict__ ad1, int n) {
    int warp = (blockIdx.x * blockDim.x + threadIdx.x) >> 5;
    if (warp >= n) return;
    int lane = threadIdx.x & 31;
    const float* row = g_h1 + (size_t)warp * F0;
    float r[8];
#pragma unroll
    for (int u = 0; u < 8; u++) r[u] = row[u * 32 + lane];
    float aw = 0.f, ar = 0.f;
#pragma unroll
    for (int u = 0; u < 8; u++) {
#pragma unroll
        for (int k2 = 0; k2 < 32; k2++) {
            float hk = __shfl_sync(FULL, r[u], k2);
            int k = u * 32 + k2;
            aw = fmaf(hk, W1[k * 32 + lane], aw);
            ar = fmaf(hk, Wr1[k * 32 + lane], ar);
        }
    }
    g_hf1[warp * 32 + lane] = aw;
    g_res1[warp * 32 + lane] = ar + br1[lane];
    float as = aw * as1[lane];
    float ad = aw * ad1[lane];
#pragma unroll
    for (int o = 16; o > 0; o >>= 1) {
        as += __shfl_down_sync(FULL, as, o);
        ad += __shfl_down_sync(FULL, ad, o);
    }
    if (lane == 0) { g_as1[warp] = as; g_ad1[warp] = ad; }
}

// ---------------- K9: layer1 agg (chunked shuffle) + LN + partial pool ----
__global__ void k_l1_agg(const float* __restrict__ bg1, const float* __restrict__ g1,
                         const float* __restrict__ b1, int n) {
    int tid = threadIdx.x;
    int wid = tid >> 5, lane = tid & 31;
    int i = blockIdx.x * 8 + wid;
    float hfinal = 0.f;
    if (i < n) {                                     // warp-uniform
        float ad = g_ad1[i];
        float w = att_w(g_as1[i] + ad);
        float acc = w * g_hf1[i * 32 + lane];
        float den = w;
        int beg = g_off[i], cnt = g_deg[i];
        for (int c0 = 0; c0 < cnt; c0 += 32) {
            int r = c0 + lane;
            int sl = 0; float wv = 0.f;
            if (r < cnt) {                           // coalesced srt + weight once/edge
                sl = g_srt[beg + r];
                wv = att_w(g_as1[sl] + ad);
            }
            int m = cnt - c0; if (m > 32) m = 32;
            for (int j = 0; j < m; j++) {
                float wj = __shfl_sync(FULL, wv, j);
                int   sj = __shfl_sync(FULL, sl, j);
                acc = fmaf(wj, g_hf1[sj * 32 + lane], acc);
                den += wj;
            }
        }
        float v = acc / (den + 1e-16f) + bg1[lane] + g_res1[i * 32 + lane];
        float s1 = v;
#pragma unroll
        for (int o = 16; o > 0; o >>= 1) s1 += __shfl_xor_sync(FULL, s1, o);
        float mn = s1 * (1.f / 32.f);
        float d = v - mn;
        float s2 = d * d;
#pragma unroll
        for (int o = 16; o > 0; o >>= 1) s2 += __shfl_xor_sync(FULL, s2, o);
        float var = s2 * (1.f / 32.f);
        hfinal = d * rsqrtf(var + LN_EPS) * g1[lane] + b1[lane];
    }
    __shared__ float sp[8][32];
    sp[wid][lane] = hfinal;
    __syncthreads();
    if (wid == 0) {
        float t = 0.f;
#pragma unroll
        for (int u = 0; u < 8; u++) t += sp[u][lane];
        g_part[blockIdx.x * 32 + lane] = t;
    }
}

// ---------------- K10: reduce partials ------------------------------------
__global__ void k_pool(int nb) {
    int tid = threadIdx.x;
    int f = tid & 31, r0 = tid >> 5;
    float s = 0.f;
    for (int b = r0; b < nb; b += 8) s += g_part[b * 32 + f];
    __shared__ float sh[256];
    sh[tid] = s;
    __syncthreads();
    if (tid < 32) {
        float t = 0.f;
#pragma unroll
        for (int u = 0; u < 8; u++) t += sh[u * 32 + tid];
        g_pool[tid] = t;
    }
}

// ---------------- K11: mean-pool scale + output linear --------------------
__global__ void k_out(const float* __restrict__ Wout, const float* __restrict__ bout,
                      float* __restrict__ out, int n) {
    int j = threadIdx.x;
    if (j >= OUT_DIM) return;
    float inv = 1.f / (float)n;
    float a = bout[j];
#pragma unroll
    for (int f = 0; f < HID; f++) a = fmaf(g_pool[f] * inv, Wout[f * OUT_DIM + j], a);
    out[j] = a;
}

// ---------------- launch ----------------------------------------------------
extern "C" void kernel_launch(void* const* d_in, const int* in_sizes, int n_in,
                              void* d_out, int out_size) {
    const float* x    = (const float*)d_in[0];
    const int*   ei   = (const int*)d_in[1];   // int64 narrowed to int32 by harness
    // d_in[2] = batch (all zeros) — unused, single graph
    const float* Win  = (const float*)d_in[3];
    const float* bin  = (const float*)d_in[4];
    const float* Wr0  = (const float*)d_in[5];
    const float* br0  = (const float*)d_in[6];
    const float* W0   = (const float*)d_in[7];
    const float* as0  = (const float*)d_in[8];
    const float* ad0  = (const float*)d_in[9];
    const float* bg0  = (const float*)d_in[10];
    const float* g0   = (const float*)d_in[11];
    const float* b0   = (const float*)d_in[12];
    const float* Wr1  = (const float*)d_in[13];
    const float* br1  = (const float*)d_in[14];
    const float* W1   = (const float*)d_in[15];
    const float* as1  = (const float*)d_in[16];
    const float* ad1  = (const float*)d_in[17];
    const float* bg1  = (const float*)d_in[18];
    const float* g1   = (const float*)d_in[19];
    const float* b1   = (const float*)d_in[20];
    const float* Wout = (const float*)d_in[21];
    const float* bout = (const float*)d_in[22];

    int n = in_sizes[0];        // x is [N,1]
    int e = in_sizes[1] / 2;    // edge_index is [2,E]
    int nb = (n + 7) / 8;
    int nb1 = (n + 1023) / 1024;

    k_in     <<<(n * HID + 255) / 256, 256>>>(x, Win, bin, n);
    k_hist   <<<(e + 255) / 256, 256>>>(ei, e, n);
    k_scan1  <<<nb1, 1024>>>(n);
    k_scan2  <<<1, 64>>>(nb1);
    k_scan3  <<<(n + 255) / 256, 256>>>(n);
    k_scatter<<<(e + 255) / 256, 256>>>(ei, e, n);
    k_prep   <<<1, 512>>>(W0, as0, ad0);
    k_logits0<<<(n + 7) / 8, 256>>>(n);
    k_l0_fused<<<n, 256>>>(W0, Wr0, br0, bg0, g0, b0);
    k_l1_gemm<<<(n * 32 + 255) / 256, 256>>>(W1, Wr1, br1, as1, ad1, n);
    k_l1_agg <<<nb, 256>>>(bg1, g1, b1, n);
    k_pool   <<<1, 256>>>(nb);
    k_out    <<<1, 32>>>(Wout, bout, (float*)d_out, n);
}